// round 3
// baseline (speedup 1.0000x reference)
#include <cuda_runtime.h>
#include <math.h>

#define BN    8
#define CINC  256
#define CMID  128
#define COUTC 256
#define HH    128
#define WW    128

// ---------------- scratch (static __device__ — allocation-free) ----------------
// g_wp[0..3]: branch weights repacked [ci][k=kh*3+kw][co(128)], scale-folded
// g_wp[4]  : w2 repacked            [ci][k][co(256)], scale-folded
__device__ float g_wp[5][294912];
__device__ float g_wp1[65536];                 // w1 repacked [ci][co(256)], scale-folded
__device__ float g_y[4][BN * CMID * HH * WW];  // branch conv outputs (post-relu)
__device__ float g_S[BN * CMID * HH * WW];     // sum of 4 scanned branches

// ---------------- weight repack (+BN scale fold) ----------------
__global__ void k_repack3(const float* __restrict__ w, const float* __restrict__ s, int which)
{
    int idx = blockIdx.x * 256 + threadIdx.x;
    if (idx >= 294912) return;
    int cin  = (which < 4) ? CINC : CMID;
    int cout = (which < 4) ? CMID : COUTC;
    int co   = idx % cout;
    int rest = idx / cout;
    int k    = rest % 9;
    int ci   = rest / 9;
    g_wp[which][idx] = w[(co * cin + ci) * 9 + k] * s[co];
}

__global__ void k_repack1(const float* __restrict__ w, const float* __restrict__ s)
{
    int idx = blockIdx.x * 256 + threadIdx.x;
    if (idx >= 65536) return;
    int co = idx & 255;
    int ci = idx >> 8;
    g_wp1[idx] = w[co * 256 + ci] * s[co];
}

// ---------------- fused 4-branch 3x3 conv + BN + relu ----------------
// One block: all 128 out-channels x one full output row (128 px) of one branch.
// grid = (H=128, B=8, branch=4), 256 threads, 8co x 8px per thread.
__global__ __launch_bounds__(256, 2) void k_conv_branch(
    const float* __restrict__ x,
    const float* __restrict__ ob0, const float* __restrict__ ob1,
    const float* __restrict__ ob2, const float* __restrict__ ob3)
{
    const int h   = blockIdx.x;
    const int b   = blockIdx.y;
    const int br  = blockIdx.z;
    const int tid = threadIdx.x;
    const int tx  = tid & 15;   // pixel group: px = tx + 16*j
    const int ty  = tid >> 4;   // co group:    co = ty*8 + i

    __shared__ float xs[4][3][130];   // 4 ci x 3 rows x (128 + 2 pad)
    __shared__ float ws[4][9][128];   // 4 ci x 9 taps x 128 co

    const float* __restrict__ wp = g_wp[br];

    float acc[8][8];
#pragma unroll
    for (int i = 0; i < 8; i++)
#pragma unroll
        for (int j = 0; j < 8; j++) acc[i][j] = 0.f;

    for (int cb = 0; cb < CINC; cb += 4) {
        __syncthreads();
        {   // weights: layout matches global exactly -> coalesced copy
            float* wl = &ws[0][0][0];
            const float* src = wp + cb * (9 * CMID);
#pragma unroll
            for (int i = 0; i < 18; i++) wl[tid + 256 * i] = src[tid + 256 * i];
        }
        for (int i = tid; i < 4 * 3 * 130; i += 256) {
            int ci  = i / 390;
            int rem = i - ci * 390;
            int r   = rem / 130;
            int c   = rem - r * 130;
            int hh  = h + r - 1;
            int wq  = c - 1;
            float v = 0.f;
            if ((unsigned)hh < (unsigned)HH && (unsigned)wq < (unsigned)WW)
                v = x[((b * CINC + cb + ci) * HH + hh) * WW + wq];
            xs[ci][r][c] = v;
        }
        __syncthreads();
#pragma unroll 1
        for (int ci = 0; ci < 4; ci++) {
#pragma unroll
            for (int kh = 0; kh < 3; kh++) {
#pragma unroll
                for (int kw = 0; kw < 3; kw++) {
                    float wv[8], xv[8];
#pragma unroll
                    for (int i = 0; i < 8; i++) wv[i] = ws[ci][kh * 3 + kw][ty * 8 + i];
#pragma unroll
                    for (int j = 0; j < 8; j++) xv[j] = xs[ci][kh][tx + 16 * j + kw];
#pragma unroll
                    for (int i = 0; i < 8; i++)
#pragma unroll
                        for (int j = 0; j < 8; j++)
                            acc[i][j] = fmaf(wv[i], xv[j], acc[i][j]);
                }
            }
        }
    }

    const float* ob = (br == 0) ? ob0 : (br == 1) ? ob1 : (br == 2) ? ob2 : ob3;
    float* yb = g_y[br];
#pragma unroll
    for (int i = 0; i < 8; i++) {
        int co = ty * 8 + i;
        float sh = ob[co];
        float* row = yb + ((b * CMID + co) * HH + h) * WW;
#pragma unroll
        for (int j = 0; j < 8; j++) {
            float v = acc[i][j] + sh;
            row[tx + 16 * j] = v > 0.f ? v : 0.f;
        }
    }
}

// ---------------- scans along W: S = revcummax_w(yl) + cummax_w(yr) ----------------
__global__ void k_scan_w()
{
    int bc = blockIdx.x;          // b*128 + c
    int h  = threadIdx.x;         // 0..127
    const float* yl = g_y[0] + bc * (HH * WW) + h * WW;
    const float* yr = g_y[1] + bc * (HH * WW) + h * WW;
    float* Sp = g_S + bc * (HH * WW) + h * WW;
    float m = -INFINITY;
    for (int w = WW - 1; w >= 0; --w) { m = fmaxf(m, yl[w]); Sp[w] = m; }
    m = -INFINITY;
    for (int w = 0; w < WW; ++w)    { m = fmaxf(m, yr[w]); Sp[w] += m; }
}

// ---------------- scans along H: S += revcummax_h(yt) + cummax_h(yb) ----------------
__global__ void k_scan_h()
{
    int bc = blockIdx.x;
    int w  = threadIdx.x;         // 0..127 (coalesced)
    const float* yt = g_y[2] + bc * (HH * WW) + w;
    const float* yv = g_y[3] + bc * (HH * WW) + w;
    float* Sp = g_S + bc * (HH * WW) + w;
    float m = -INFINITY;
    for (int hq = HH - 1; hq >= 0; --hq) { m = fmaxf(m, yt[hq * WW]); Sp[hq * WW] += m; }
    m = -INFINITY;
    for (int hq = 0; hq < HH; ++hq)      { m = fmaxf(m, yv[hq * WW]); Sp[hq * WW] += m; }
}

// ---------------- conv2 3x3 over S + 1x1 skip over x + relu -> out ----------------
// grid = (H=128, B=8, cotile=2), 256 threads, tile = 128co x 128px.
__global__ __launch_bounds__(256, 2) void k_conv_out(
    const float* __restrict__ x,
    const float* __restrict__ o2v, const float* __restrict__ o1v,
    float* __restrict__ out)
{
    const int h   = blockIdx.x;
    const int b   = blockIdx.y;
    const int ct  = blockIdx.z;  // 0..1 (co tile of 128)
    const int tid = threadIdx.x;
    const int tx  = tid & 15;
    const int ty  = tid >> 4;

    __shared__ float xs[4][3][130];
    __shared__ float ws[4][9][128];
    __shared__ float xs1[16][128];
    __shared__ float ws1[16][128];

    float acc[8][8];
#pragma unroll
    for (int i = 0; i < 8; i++)
#pragma unroll
        for (int j = 0; j < 8; j++) acc[i][j] = 0.f;

    // ---- Part A: 3x3 conv over g_S (128 input channels) ----
    for (int cb = 0; cb < CMID; cb += 4) {
        __syncthreads();
        {
            float* wl = &ws[0][0][0];
#pragma unroll
            for (int ii = 0; ii < 18; ii++) {
                int i    = tid + 256 * ii;        // [ci][k][co128] linear
                int co   = i & 127;
                int rest = i >> 7;
                int k    = rest % 9;
                int ci   = rest / 9;
                wl[i] = g_wp[4][((cb + ci) * 9 + k) * COUTC + ct * 128 + co];
            }
        }
        for (int i = tid; i < 4 * 3 * 130; i += 256) {
            int ci  = i / 390;
            int rem = i - ci * 390;
            int r   = rem / 130;
            int c   = rem - r * 130;
            int hh  = h + r - 1;
            int wq  = c - 1;
            float v = 0.f;
            if ((unsigned)hh < (unsigned)HH && (unsigned)wq < (unsigned)WW)
                v = g_S[((b * CMID + cb + ci) * HH + hh) * WW + wq];
            xs[ci][r][c] = v;
        }
        __syncthreads();
#pragma unroll 1
        for (int ci = 0; ci < 4; ci++) {
#pragma unroll
            for (int kh = 0; kh < 3; kh++) {
#pragma unroll
                for (int kw = 0; kw < 3; kw++) {
                    float wv[8], xv[8];
#pragma unroll
                    for (int i = 0; i < 8; i++) wv[i] = ws[ci][kh * 3 + kw][ty * 8 + i];
#pragma unroll
                    for (int j = 0; j < 8; j++) xv[j] = xs[ci][kh][tx + 16 * j + kw];
#pragma unroll
                    for (int i = 0; i < 8; i++)
#pragma unroll
                        for (int j = 0; j < 8; j++)
                            acc[i][j] = fmaf(wv[i], xv[j], acc[i][j]);
                }
            }
        }
    }

    // ---- Part B: 1x1 skip conv over x (256 input channels) ----
    for (int cb = 0; cb < CINC; cb += 16) {
        __syncthreads();
#pragma unroll
        for (int ii = 0; ii < 8; ii++) {
            int i  = tid + 256 * ii;              // 2048 elements each
            int ci = i >> 7;
            int wq = i & 127;
            xs1[ci][wq] = x[((b * CINC + cb + ci) * HH + h) * WW + wq];
            ws1[ci][wq] = g_wp1[(cb + ci) * COUTC + ct * 128 + wq];
        }
        __syncthreads();
#pragma unroll 1
        for (int ci = 0; ci < 16; ci++) {
            float wv[8], xv[8];
#pragma unroll
            for (int i = 0; i < 8; i++) wv[i] = ws1[ci][ty * 8 + i];
#pragma unroll
            for (int j = 0; j < 8; j++) xv[j] = xs1[ci][tx + 16 * j];
#pragma unroll
            for (int i = 0; i < 8; i++)
#pragma unroll
                for (int j = 0; j < 8; j++)
                    acc[i][j] = fmaf(wv[i], xv[j], acc[i][j]);
        }
    }

    // ---- epilogue: + (o2 + o1), relu, store ----
#pragma unroll
    for (int i = 0; i < 8; i++) {
        int co = ct * 128 + ty * 8 + i;
        float sh = o2v[co] + o1v[co];
        float* row = out + ((b * COUTC + co) * HH + h) * WW;
#pragma unroll
        for (int j = 0; j < 8; j++) {
            float v = acc[i][j] + sh;
            row[tx + 16 * j] = v > 0.f ? v : 0.f;
        }
    }
}

// ---------------- launch ----------------
extern "C" void kernel_launch(void* const* d_in, const int* in_sizes, int n_in,
                              void* d_out, int out_size)
{
    const float* x   = (const float*)d_in[0];
    const float* w_l = (const float*)d_in[1];
    const float* s_l = (const float*)d_in[2];
    const float* o_l = (const float*)d_in[3];
    const float* w_r = (const float*)d_in[4];
    const float* s_r = (const float*)d_in[5];
    const float* o_r = (const float*)d_in[6];
    const float* w_t = (const float*)d_in[7];
    const float* s_t = (const float*)d_in[8];
    const float* o_t = (const float*)d_in[9];
    const float* w_b = (const float*)d_in[10];
    const float* s_b = (const float*)d_in[11];
    const float* o_b = (const float*)d_in[12];
    const float* w2  = (const float*)d_in[13];
    const float* s2  = (const float*)d_in[14];
    const float* o2  = (const float*)d_in[15];
    const float* w1  = (const float*)d_in[16];
    const float* s1  = (const float*)d_in[17];
    const float* o1  = (const float*)d_in[18];
    float* out = (float*)d_out;

    k_repack3<<<1152, 256>>>(w_l, s_l, 0);
    k_repack3<<<1152, 256>>>(w_r, s_r, 1);
    k_repack3<<<1152, 256>>>(w_t, s_t, 2);
    k_repack3<<<1152, 256>>>(w_b, s_b, 3);
    k_repack3<<<1152, 256>>>(w2,  s2,  4);
    k_repack1<<<256, 256>>>(w1, s1);

    dim3 g1(HH, BN, 4);
    k_conv_branch<<<g1, 256>>>(x, o_l, o_r, o_t, o_b);
    k_scan_w<<<BN * CMID, 128>>>();
    k_scan_h<<<BN * CMID, 128>>>();
    dim3 g3(HH, BN, 2);
    k_conv_out<<<g3, 256>>>(x, o2, o1, out);
}

// round 4
// speedup vs baseline: 1.0953x; 1.0953x over previous
#include <cuda_runtime.h>
#include <math.h>

#define BN    8
#define CINC  256
#define CMID  128
#define COUTC 256
#define HH    128
#define WW    128

typedef unsigned long long u64;

// packed f32x2 helpers (Blackwell FFMA2 — only reachable via PTX)
__device__ __forceinline__ u64 pack2(float a, float b) {
    u64 r; asm("mov.b64 %0, {%1,%2};" : "=l"(r) : "f"(a), "f"(b)); return r;
}
__device__ __forceinline__ void unpack2(u64 v, float& a, float& b) {
    asm("mov.b64 {%0,%1}, %2;" : "=f"(a), "=f"(b) : "l"(v));
}
#define FMA2(acc, a, b) asm("fma.rn.f32x2 %0, %1, %2, %0;" : "+l"(acc) : "l"(a), "l"(b))

// ---------------- scratch (static __device__ — allocation-free) ----------------
__device__ float g_wp[5][294912];              // [ci][k][co], scale-folded
__device__ float g_wp1[65536];                 // w1 [ci][co(256)], scale-folded
__device__ float g_y[4][BN * CMID * HH * WW];  // branch conv outputs (post-relu)
__device__ float g_S[BN * CMID * HH * WW];     // sum of 4 scanned branches

// ---------------- weight repack (+BN scale fold) ----------------
__global__ void k_repack3(const float* __restrict__ w, const float* __restrict__ s, int which)
{
    int idx = blockIdx.x * 256 + threadIdx.x;
    if (idx >= 294912) return;
    int cin  = (which < 4) ? CINC : CMID;
    int cout = (which < 4) ? CMID : COUTC;
    int co   = idx % cout;
    int rest = idx / cout;
    int k    = rest % 9;
    int ci   = rest / 9;
    g_wp[which][idx] = w[(co * cin + ci) * 9 + k] * s[co];
}

__global__ void k_repack1(const float* __restrict__ w, const float* __restrict__ s)
{
    int idx = blockIdx.x * 256 + threadIdx.x;
    if (idx >= 65536) return;
    int co = idx & 255;
    int ci = idx >> 8;
    g_wp1[idx] = w[co * 256 + ci] * s[co];
}

// ---------------- fused 4-branch 3x3 conv + BN + relu (FFMA2) ----------------
// grid = (H=128, B=8, branch=4), 256 threads.
// Thread tile: 8 co (as 4 packed pairs) x 8 px. co = ty*8 + 2*i2 + {0,1}, px = tx + 16*j.
__global__ __launch_bounds__(256, 2) void k_conv_branch(
    const float* __restrict__ x,
    const float* __restrict__ ob0, const float* __restrict__ ob1,
    const float* __restrict__ ob2, const float* __restrict__ ob3)
{
    const int h   = blockIdx.x;
    const int b   = blockIdx.y;
    const int br  = blockIdx.z;
    const int tid = threadIdx.x;
    const int tx  = tid & 15;
    const int ty  = tid >> 4;

    __shared__ float xs[4][3][130];
    __shared__ float ws[4][9][128];

    const float* __restrict__ wp = g_wp[br];

    u64 acc[4][8];
#pragma unroll
    for (int i = 0; i < 4; i++)
#pragma unroll
        for (int j = 0; j < 8; j++) acc[i][j] = 0ULL;

    for (int cb = 0; cb < CINC; cb += 4) {
        __syncthreads();
        {   // weights: coalesced copy, layout identical to global
            float* wl = &ws[0][0][0];
            const float* src = wp + cb * (9 * CMID);
#pragma unroll
            for (int i = 0; i < 18; i++) wl[tid + 256 * i] = src[tid + 256 * i];
        }
        for (int i = tid; i < 4 * 3 * 130; i += 256) {
            int ci  = i / 390;
            int rem = i - ci * 390;
            int r   = rem / 130;
            int c   = rem - r * 130;
            int hh  = h + r - 1;
            int wq  = c - 1;
            float v = 0.f;
            if ((unsigned)hh < (unsigned)HH && (unsigned)wq < (unsigned)WW)
                v = x[((b * CINC + cb + ci) * HH + hh) * WW + wq];
            xs[ci][r][c] = v;
        }
        __syncthreads();
#pragma unroll 1
        for (int ci = 0; ci < 4; ci++) {
#pragma unroll
            for (int kh = 0; kh < 3; kh++) {
#pragma unroll
                for (int kw = 0; kw < 3; kw++) {
                    // weight pairs: adjacent co -> one aligned 8B shared load each
                    const u64* w2 = (const u64*)&ws[ci][kh * 3 + kw][ty * 8];
                    u64 wv[4];
#pragma unroll
                    for (int i = 0; i < 4; i++) wv[i] = w2[i];
#pragma unroll
                    for (int j = 0; j < 8; j++) {
                        float xj = xs[ci][kh][tx + 16 * j + kw];
                        u64 xx = pack2(xj, xj);
#pragma unroll
                        for (int i = 0; i < 4; i++) FMA2(acc[i][j], wv[i], xx);
                    }
                }
            }
        }
    }

    const float* ob = (br == 0) ? ob0 : (br == 1) ? ob1 : (br == 2) ? ob2 : ob3;
    float* yb = g_y[br];
#pragma unroll
    for (int i = 0; i < 4; i++) {
        int co = ty * 8 + 2 * i;
        float sh0 = ob[co], sh1 = ob[co + 1];
        float* row0 = yb + ((b * CMID + co)     * HH + h) * WW;
        float* row1 = yb + ((b * CMID + co + 1) * HH + h) * WW;
#pragma unroll
        for (int j = 0; j < 8; j++) {
            float v0, v1;
            unpack2(acc[i][j], v0, v1);
            v0 += sh0; v1 += sh1;
            row0[tx + 16 * j] = v0 > 0.f ? v0 : 0.f;
            row1[tx + 16 * j] = v1 > 0.f ? v1 : 0.f;
        }
    }
}

// ---------------- scans along W ----------------
__global__ void k_scan_w()
{
    int bc = blockIdx.x;
    int h  = threadIdx.x;
    const float* yl = g_y[0] + bc * (HH * WW) + h * WW;
    const float* yr = g_y[1] + bc * (HH * WW) + h * WW;
    float* Sp = g_S + bc * (HH * WW) + h * WW;
    float m = -INFINITY;
    for (int w = WW - 1; w >= 0; --w) { m = fmaxf(m, yl[w]); Sp[w] = m; }
    m = -INFINITY;
    for (int w = 0; w < WW; ++w)    { m = fmaxf(m, yr[w]); Sp[w] += m; }
}

// ---------------- scans along H ----------------
__global__ void k_scan_h()
{
    int bc = blockIdx.x;
    int w  = threadIdx.x;
    const float* yt = g_y[2] + bc * (HH * WW) + w;
    const float* yv = g_y[3] + bc * (HH * WW) + w;
    float* Sp = g_S + bc * (HH * WW) + w;
    float m = -INFINITY;
    for (int hq = HH - 1; hq >= 0; --hq) { m = fmaxf(m, yt[hq * WW]); Sp[hq * WW] += m; }
    m = -INFINITY;
    for (int hq = 0; hq < HH; ++hq)      { m = fmaxf(m, yv[hq * WW]); Sp[hq * WW] += m; }
}

// ---------------- conv2 3x3 over S + 1x1 skip over x + relu -> out (FFMA2) ----------------
// grid = (H=128, B=8, cotile=2), 256 threads.
__global__ __launch_bounds__(256, 2) void k_conv_out(
    const float* __restrict__ x,
    const float* __restrict__ o2v, const float* __restrict__ o1v,
    float* __restrict__ out)
{
    const int h   = blockIdx.x;
    const int b   = blockIdx.y;
    const int ct  = blockIdx.z;
    const int tid = threadIdx.x;
    const int tx  = tid & 15;
    const int ty  = tid >> 4;

    __shared__ float xs[4][3][130];
    __shared__ float ws[4][9][128];
    __shared__ float xs1[16][128];
    __shared__ float ws1[16][128];

    u64 acc[4][8];
#pragma unroll
    for (int i = 0; i < 4; i++)
#pragma unroll
        for (int j = 0; j < 8; j++) acc[i][j] = 0ULL;

    // ---- Part A: 3x3 conv over g_S (128 input channels) ----
    for (int cb = 0; cb < CMID; cb += 4) {
        __syncthreads();
        {
            float* wl = &ws[0][0][0];
#pragma unroll
            for (int ii = 0; ii < 18; ii++) {
                int i    = tid + 256 * ii;
                int co   = i & 127;
                int rest = i >> 7;
                int k    = rest % 9;
                int ci   = rest / 9;
                wl[i] = g_wp[4][((cb + ci) * 9 + k) * COUTC + ct * 128 + co];
            }
        }
        for (int i = tid; i < 4 * 3 * 130; i += 256) {
            int ci  = i / 390;
            int rem = i - ci * 390;
            int r   = rem / 130;
            int c   = rem - r * 130;
            int hh  = h + r - 1;
            int wq  = c - 1;
            float v = 0.f;
            if ((unsigned)hh < (unsigned)HH && (unsigned)wq < (unsigned)WW)
                v = g_S[((b * CMID + cb + ci) * HH + hh) * WW + wq];
            xs[ci][r][c] = v;
        }
        __syncthreads();
#pragma unroll 1
        for (int ci = 0; ci < 4; ci++) {
#pragma unroll
            for (int kh = 0; kh < 3; kh++) {
#pragma unroll
                for (int kw = 0; kw < 3; kw++) {
                    const u64* w2 = (const u64*)&ws[ci][kh * 3 + kw][ty * 8];
                    u64 wv[4];
#pragma unroll
                    for (int i = 0; i < 4; i++) wv[i] = w2[i];
#pragma unroll
                    for (int j = 0; j < 8; j++) {
                        float xj = xs[ci][kh][tx + 16 * j + kw];
                        u64 xx = pack2(xj, xj);
#pragma unroll
                        for (int i = 0; i < 4; i++) FMA2(acc[i][j], wv[i], xx);
                    }
                }
            }
        }
    }

    // ---- Part B: 1x1 skip conv over x (256 input channels) ----
    for (int cb = 0; cb < CINC; cb += 16) {
        __syncthreads();
#pragma unroll
        for (int ii = 0; ii < 8; ii++) {
            int i  = tid + 256 * ii;
            int ci = i >> 7;
            int wq = i & 127;
            xs1[ci][wq] = x[((b * CINC + cb + ci) * HH + h) * WW + wq];
            ws1[ci][wq] = g_wp1[(cb + ci) * COUTC + ct * 128 + wq];
        }
        __syncthreads();
#pragma unroll 1
        for (int ci = 0; ci < 16; ci++) {
            const u64* w2 = (const u64*)&ws1[ci][ty * 8];
            u64 wv[4];
#pragma unroll
            for (int i = 0; i < 4; i++) wv[i] = w2[i];
#pragma unroll
            for (int j = 0; j < 8; j++) {
                float xj = xs1[ci][tx + 16 * j];
                u64 xx = pack2(xj, xj);
#pragma unroll
                for (int i = 0; i < 4; i++) FMA2(acc[i][j], wv[i], xx);
            }
        }
    }

    // ---- epilogue: + (o2 + o1), relu, store ----
#pragma unroll
    for (int i = 0; i < 4; i++) {
        int co = ct * 128 + ty * 8 + 2 * i;
        float sh0 = o2v[co] + o1v[co];
        float sh1 = o2v[co + 1] + o1v[co + 1];
        float* row0 = out + ((b * COUTC + co)     * HH + h) * WW;
        float* row1 = out + ((b * COUTC + co + 1) * HH + h) * WW;
#pragma unroll
        for (int j = 0; j < 8; j++) {
            float v0, v1;
            unpack2(acc[i][j], v0, v1);
            v0 += sh0; v1 += sh1;
            row0[tx + 16 * j] = v0 > 0.f ? v0 : 0.f;
            row1[tx + 16 * j] = v1 > 0.f ? v1 : 0.f;
        }
    }
}

// ---------------- launch ----------------
extern "C" void kernel_launch(void* const* d_in, const int* in_sizes, int n_in,
                              void* d_out, int out_size)
{
    const float* x   = (const float*)d_in[0];
    const float* w_l = (const float*)d_in[1];
    const float* s_l = (const float*)d_in[2];
    const float* o_l = (const float*)d_in[3];
    const float* w_r = (const float*)d_in[4];
    const float* s_r = (const float*)d_in[5];
    const float* o_r = (const float*)d_in[6];
    const float* w_t = (const float*)d_in[7];
    const float* s_t = (const float*)d_in[8];
    const float* o_t = (const float*)d_in[9];
    const float* w_b = (const float*)d_in[10];
    const float* s_b = (const float*)d_in[11];
    const float* o_b = (const float*)d_in[12];
    const float* w2  = (const float*)d_in[13];
    const float* s2  = (const float*)d_in[14];
    const float* o2  = (const float*)d_in[15];
    const float* w1  = (const float*)d_in[16];
    const float* s1  = (const float*)d_in[17];
    const float* o1  = (const float*)d_in[18];
    float* out = (float*)d_out;

    k_repack3<<<1152, 256>>>(w_l, s_l, 0);
    k_repack3<<<1152, 256>>>(w_r, s_r, 1);
    k_repack3<<<1152, 256>>>(w_t, s_t, 2);
    k_repack3<<<1152, 256>>>(w_b, s_b, 3);
    k_repack3<<<1152, 256>>>(w2,  s2,  4);
    k_repack1<<<256, 256>>>(w1, s1);

    dim3 g1(HH, BN, 4);
    k_conv_branch<<<g1, 256>>>(x, o_l, o_r, o_t, o_b);
    k_scan_w<<<BN * CMID, 128>>>();
    k_scan_h<<<BN * CMID, 128>>>();
    dim3 g3(HH, BN, 2);
    k_conv_out<<<g3, 256>>>(x, o2, o1, out);
}

// round 6
// speedup vs baseline: 2.1007x; 1.9179x over previous
#include <cuda_runtime.h>
#include <cuda_bf16.h>
#include <cstdint>
#include <math.h>

#define BN    8
#define CINC  256
#define CMID  128
#define COUTC 256
#define HH    128
#define WW    128

typedef uint32_t u32;

// ---------------- scratch (static __device__ — allocation-free) ----------------
__device__ float g_y[4][BN * CMID * HH * WW];  // branch conv outputs (post-relu)
__device__ float g_S[BN * CMID * HH * WW];     // sum of 4 scanned branches
// bf16-split weights: branch [tap=br*9+kh*3+kw][co=128][cipair]
__device__ __nv_bfloat162 g_wAh[36 * 128 * 128];
__device__ __nv_bfloat162 g_wAl[36 * 128 * 128];
__device__ __nv_bfloat162 g_w2h[9 * 256 * 64];   // [t][co=256][cipair=64]
__device__ __nv_bfloat162 g_w2l[9 * 256 * 64];
__device__ __nv_bfloat162 g_w1h[256 * 128];      // [co=256][cipair=128]
__device__ __nv_bfloat162 g_w1l[256 * 128];

// ---------------- helpers ----------------
__device__ __forceinline__ u32 smem_u32(const void* p) {
    u32 a;
    asm("{ .reg .u64 t; cvta.to.shared.u64 t, %1; cvt.u32.u64 %0, t; }" : "=r"(a) : "l"(p));
    return a;
}

// XOR swizzle: 16B-chunk bits [6:4] ^= row bits [9:7]  (rows are 128B)
#define SWZ(off) ((off) ^ (((off) >> 3) & 0x70))

__device__ __forceinline__ void ldm_x4(u32* r, u32 addr) {
    asm volatile("ldmatrix.sync.aligned.m8n8.x4.shared.b16 {%0,%1,%2,%3}, [%4];"
                 : "=r"(r[0]), "=r"(r[1]), "=r"(r[2]), "=r"(r[3]) : "r"(addr));
}
__device__ __forceinline__ void mma16816(float* d, const u32* a, const u32* b) {
    asm volatile("mma.sync.aligned.m16n8k16.row.col.f32.bf16.bf16.f32 "
                 "{%0,%1,%2,%3}, {%4,%5,%6,%7}, {%8,%9}, {%0,%1,%2,%3};"
                 : "+f"(d[0]), "+f"(d[1]), "+f"(d[2]), "+f"(d[3])
                 : "r"(a[0]), "r"(a[1]), "r"(a[2]), "r"(a[3]), "r"(b[0]), "r"(b[1]));
}

// smem layout: four 128x64 bf16 tiles (16KB each)
#define OFF_AH 0
#define OFF_AL 16384
#define OFF_BH 32768
#define OFF_BL 49152
#define SMEM_BYTES 65536

__device__ __forceinline__ void split2(float v0, float v1, u32 sb, u32 off) {
    __nv_bfloat16 h0 = __float2bfloat16(v0), h1 = __float2bfloat16(v1);
    __nv_bfloat16 l0 = __float2bfloat16(v0 - __bfloat162float(h0));
    __nv_bfloat16 l1 = __float2bfloat16(v1 - __bfloat162float(h1));
    u32 sw = SWZ(off);
    u32 hv, lv;
    asm("mov.b32 %0, {%1, %2};" : "=r"(hv) : "h"(*(unsigned short*)&h0), "h"(*(unsigned short*)&h1));
    asm("mov.b32 %0, {%1, %2};" : "=r"(lv) : "h"(*(unsigned short*)&l0), "h"(*(unsigned short*)&l1));
    asm volatile("st.shared.b32 [%0], %1;" :: "r"(sb + OFF_BH + sw), "r"(hv) : "memory");
    asm volatile("st.shared.b32 [%0], %1;" :: "r"(sb + OFF_BL + sw), "r"(lv) : "memory");
}

// ---------------- weight repack (+BN scale fold, bf16 hi/lo split) ----------------
__global__ void k_repack_br(const float* __restrict__ w, const float* __restrict__ s, int br)
{
    int slot = blockIdx.x * 256 + threadIdx.x;       // 9*128*128
    if (slot >= 147456) return;
    int pair = slot & 127;
    int co   = (slot >> 7) & 127;
    int t    = slot >> 14;
    int kh = t / 3, kw = t % 3;
    int ci = pair * 2;
    float sc = s[co];
    float v0 = w[((co * CINC + ci)     * 3 + kh) * 3 + kw] * sc;
    float v1 = w[((co * CINC + ci + 1) * 3 + kh) * 3 + kw] * sc;
    __nv_bfloat16 h0 = __float2bfloat16(v0), h1 = __float2bfloat16(v1);
    __nv_bfloat16 l0 = __float2bfloat16(v0 - __bfloat162float(h0));
    __nv_bfloat16 l1 = __float2bfloat16(v1 - __bfloat162float(h1));
    int idx = ((br * 9 + t) * 128 + co) * 128 + pair;
    g_wAh[idx] = __halves2bfloat162(h0, h1);
    g_wAl[idx] = __halves2bfloat162(l0, l1);
}

__global__ void k_repack_w2(const float* __restrict__ w, const float* __restrict__ s)
{
    int slot = blockIdx.x * 256 + threadIdx.x;       // 9*256*64
    if (slot >= 147456) return;
    int pair = slot & 63;
    int co   = (slot >> 6) & 255;
    int t    = slot >> 14;
    int kh = t / 3, kw = t % 3;
    int ci = pair * 2;
    float sc = s[co];
    float v0 = w[((co * CMID + ci)     * 3 + kh) * 3 + kw] * sc;
    float v1 = w[((co * CMID + ci + 1) * 3 + kh) * 3 + kw] * sc;
    __nv_bfloat16 h0 = __float2bfloat16(v0), h1 = __float2bfloat16(v1);
    __nv_bfloat16 l0 = __float2bfloat16(v0 - __bfloat162float(h0));
    __nv_bfloat16 l1 = __float2bfloat16(v1 - __bfloat162float(h1));
    int idx = (t * 256 + co) * 64 + pair;
    g_w2h[idx] = __halves2bfloat162(h0, h1);
    g_w2l[idx] = __halves2bfloat162(l0, l1);
}

__global__ void k_repack_w1(const float* __restrict__ w, const float* __restrict__ s)
{
    int slot = blockIdx.x * 256 + threadIdx.x;       // 256*128
    if (slot >= 32768) return;
    int pair = slot & 127;
    int co   = slot >> 7;
    int ci = pair * 2;
    float sc = s[co];
    float v0 = w[co * CINC + ci]     * sc;
    float v1 = w[co * CINC + ci + 1] * sc;
    __nv_bfloat16 h0 = __float2bfloat16(v0), h1 = __float2bfloat16(v1);
    __nv_bfloat16 l0 = __float2bfloat16(v0 - __bfloat162float(h0));
    __nv_bfloat16 l1 = __float2bfloat16(v1 - __bfloat162float(h1));
    g_w1h[co * 128 + pair] = __halves2bfloat162(h0, h1);
    g_w1l[co * 128 + pair] = __halves2bfloat162(l0, l1);
}

// ---------------- tile builds (512 threads) ----------------
// A tile: 128 co rows x 64 bf16 cols, swizzled; hi->OFF_AH lo->OFF_AL
__device__ __forceinline__ void build_A(u32 sb, int tid,
                                        const __nv_bfloat162* __restrict__ wh,
                                        const __nv_bfloat162* __restrict__ wl,
                                        int row_stride_pairs, int pair0)
{
#pragma unroll
    for (int q = 0; q < 8; q++) {
        int slot = tid + 512 * q;            // 4096 slots
        int co  = slot >> 5;
        int cip = slot & 31;
        int src = co * row_stride_pairs + pair0 + cip;
        u32 sw  = SWZ((u32)(co * 128 + 4 * cip));
        u32 hv = *(const u32*)&wh[src];
        u32 lv = *(const u32*)&wl[src];
        asm volatile("st.shared.b32 [%0], %1;" :: "r"(sb + OFF_AH + sw), "r"(hv) : "memory");
        asm volatile("st.shared.b32 [%0], %1;" :: "r"(sb + OFF_AL + sw), "r"(lv) : "memory");
    }
}

// B tile: 128 px rows x 64 bf16 cols (ci), split from fp32 with shift+pad
__device__ __forceinline__ void build_B(u32 sb, int tid, const float* __restrict__ src,
                                        int nchan, int b, int c0, int srow, int kwm1)
{
    int p = tid & 127;
    int g = tid >> 7;                        // 0..3
    int px = p + kwm1;
    bool valid = (srow >= 0) && (srow < HH) && (px >= 0) && (px < WW);
    const float* base = src + ((size_t)(b * nchan + c0) * HH + srow) * WW + px;
#pragma unroll
    for (int q = 0; q < 8; q++) {
        int cil = g * 16 + 2 * q;            // even col 0..62
        float v0 = 0.f, v1 = 0.f;
        if (valid) {
            v0 = base[(size_t)cil * (HH * WW)];
            v1 = base[(size_t)(cil + 1) * (HH * WW)];
        }
        split2(v0, v1, sb, (u32)(p * 128 + 2 * cil));
    }
}

// ---------------- mma over one 64-k chunk (per warp: 32co x 32px tile) ----------------
__device__ __forceinline__ void mma_chunk(u32 sb, int wm, int wn, int lid, float acc[2][4][4])
{
    const u32 lrow = (u32)(lid & 15) * 128;
    const u32 lkh  = (u32)((lid >> 4) << 4);
#pragma unroll
    for (int ks = 0; ks < 4; ks++) {
        const u32 kb = (u32)(ks * 32) + lkh;
        u32 ah[2][4], al[2][4], bh[2][4], bl[2][4];
#pragma unroll
        for (int mt = 0; mt < 2; mt++) {
            u32 off = SWZ((u32)((wm * 32 + mt * 16) * 128) + lrow + kb);
            ldm_x4(ah[mt], sb + OFF_AH + off);
            ldm_x4(al[mt], sb + OFF_AL + off);
        }
#pragma unroll
        for (int bt = 0; bt < 2; bt++) {
            u32 off = SWZ((u32)((wn * 32 + bt * 16) * 128) + lrow + kb);
            ldm_x4(bh[bt], sb + OFF_BH + off);
            ldm_x4(bl[bt], sb + OFF_BL + off);
        }
#pragma unroll
        for (int mt = 0; mt < 2; mt++)
#pragma unroll
            for (int bt = 0; bt < 2; bt++)
#pragma unroll
                for (int j = 0; j < 2; j++) {
                    u32 BH2[2] = { bh[bt][j], bh[bt][j + 2] };
                    u32 BL2[2] = { bl[bt][j], bl[bt][j + 2] };
                    float* d = acc[mt][bt * 2 + j];
                    mma16816(d, ah[mt], BH2);
                    mma16816(d, ah[mt], BL2);
                    mma16816(d, al[mt], BH2);
                }
    }
}

// ---------------- fused 4-branch 3x3 conv + BN + relu (HMMA) ----------------
// grid = (H=128, B=8, br=4), 512 threads; block tile 128co x 128px
__global__ __launch_bounds__(512, 1)
void k_conv_branch(const float* __restrict__ x,
                   const float* __restrict__ ob0, const float* __restrict__ ob1,
                   const float* __restrict__ ob2, const float* __restrict__ ob3)
{
    extern __shared__ char smem_raw[];
    u32 sb = smem_u32(smem_raw);
    const int h  = blockIdx.x;
    const int b  = blockIdx.y;
    const int br = blockIdx.z;
    const int tid = threadIdx.x;
    const int wid = tid >> 5, lid = tid & 31;
    const int wm = wid >> 2, wn = wid & 3;

    float acc[2][4][4];
#pragma unroll
    for (int i = 0; i < 2; i++)
#pragma unroll
        for (int j = 0; j < 4; j++)
#pragma unroll
            for (int k = 0; k < 4; k++) acc[i][j][k] = 0.f;

    for (int kh = 0; kh < 3; kh++) {
        int srow = h + kh - 1;
        for (int kw = 0; kw < 3; kw++) {
            int tap = br * 9 + kh * 3 + kw;
            const __nv_bfloat162* wh = g_wAh + (size_t)tap * 128 * 128;
            const __nv_bfloat162* wl = g_wAl + (size_t)tap * 128 * 128;
            for (int c0 = 0; c0 < CINC; c0 += 64) {
                __syncthreads();
                build_A(sb, tid, wh, wl, 128, c0 >> 1);
                build_B(sb, tid, x, CINC, b, c0, srow, kw - 1);
                __syncthreads();
                mma_chunk(sb, wm, wn, lid, acc);
            }
        }
    }

    const float* ob = (br == 0) ? ob0 : (br == 1) ? ob1 : (br == 2) ? ob2 : ob3;
    float* yb = g_y[br];
#pragma unroll
    for (int mt = 0; mt < 2; mt++) {
        int r0 = wm * 32 + mt * 16 + (lid >> 2);
#pragma unroll
        for (int half = 0; half < 2; half++) {
            int co = r0 + half * 8;
            float sh = ob[co];
            float* row = yb + ((size_t)(b * CMID + co) * HH + h) * WW;
#pragma unroll
            for (int nf = 0; nf < 4; nf++) {
                int px = wn * 32 + nf * 8 + 2 * (lid & 3);
                float2 v;
                v.x = fmaxf(acc[mt][nf][half * 2 + 0] + sh, 0.f);
                v.y = fmaxf(acc[mt][nf][half * 2 + 1] + sh, 0.f);
                *(float2*)(row + px) = v;
            }
        }
    }
}

// ---------------- scans along W ----------------
__global__ void k_scan_w()
{
    int bc = blockIdx.x;
    int h  = threadIdx.x;
    const float* yl = g_y[0] + (size_t)bc * (HH * WW) + h * WW;
    const float* yr = g_y[1] + (size_t)bc * (HH * WW) + h * WW;
    float* Sp = g_S + (size_t)bc * (HH * WW) + h * WW;
    float m = -INFINITY;
    for (int w = WW - 1; w >= 0; --w) { m = fmaxf(m, yl[w]); Sp[w] = m; }
    m = -INFINITY;
    for (int w = 0; w < WW; ++w)    { m = fmaxf(m, yr[w]); Sp[w] += m; }
}

// ---------------- scans along H ----------------
__global__ void k_scan_h()
{
    int bc = blockIdx.x;
    int w  = threadIdx.x;
    const float* yt = g_y[2] + (size_t)bc * (HH * WW) + w;
    const float* yv = g_y[3] + (size_t)bc * (HH * WW) + w;
    float* Sp = g_S + (size_t)bc * (HH * WW) + w;
    float m = -INFINITY;
    for (int hq = HH - 1; hq >= 0; --hq) { m = fmaxf(m, yt[hq * WW]); Sp[hq * WW] += m; }
    m = -INFINITY;
    for (int hq = 0; hq < HH; ++hq)      { m = fmaxf(m, yv[hq * WW]); Sp[hq * WW] += m; }
}

// ---------------- conv2 3x3 over S + 1x1 skip over x + relu -> out (HMMA) ----------------
// grid = (H=128, B=8, ct=2), 512 threads
__global__ __launch_bounds__(512, 1)
void k_conv_out(const float* __restrict__ x,
                const float* __restrict__ o2v, const float* __restrict__ o1v,
                float* __restrict__ out)
{
    extern __shared__ char smem_raw[];
    u32 sb = smem_u32(smem_raw);
    const int h  = blockIdx.x;
    const int b  = blockIdx.y;
    const int ct = blockIdx.z;
    const int tid = threadIdx.x;
    const int wid = tid >> 5, lid = tid & 31;
    const int wm = wid >> 2, wn = wid & 3;

    float acc[2][4][4];
#pragma unroll
    for (int i = 0; i < 2; i++)
#pragma unroll
        for (int j = 0; j < 4; j++)
#pragma unroll
            for (int k = 0; k < 4; k++) acc[i][j][k] = 0.f;

    // phase 1: 3x3 conv over g_S (128 ci)
    for (int kh = 0; kh < 3; kh++) {
        int srow = h + kh - 1;
        for (int kw = 0; kw < 3; kw++) {
            int t = kh * 3 + kw;
            const __nv_bfloat162* wh = g_w2h + ((size_t)t * 256 + ct * 128) * 64;
            const __nv_bfloat162* wl = g_w2l + ((size_t)t * 256 + ct * 128) * 64;
            for (int c0 = 0; c0 < CMID; c0 += 64) {
                __syncthreads();
                build_A(sb, tid, wh, wl, 64, c0 >> 1);
                build_B(sb, tid, g_S, CMID, b, c0, srow, kw - 1);
                __syncthreads();
                mma_chunk(sb, wm, wn, lid, acc);
            }
        }
    }
    // phase 2: 1x1 skip over x (256 ci)
    {
        const __nv_bfloat162* wh = g_w1h + (size_t)(ct * 128) * 128;
        const __nv_bfloat162* wl = g_w1l + (size_t)(ct * 128) * 128;
        for (int c0 = 0; c0 < CINC; c0 += 64) {
            __syncthreads();
            build_A(sb, tid, wh, wl, 128, c0 >> 1);
            build_B(sb, tid, x, CINC, b, c0, h, 0);
            __syncthreads();
            mma_chunk(sb, wm, wn, lid, acc);
        }
    }

#pragma unroll
    for (int mt = 0; mt < 2; mt++) {
        int r0 = wm * 32 + mt * 16 + (lid >> 2);
#pragma unroll
        for (int half = 0; half < 2; half++) {
            int co = ct * 128 + r0 + half * 8;
            float sh = o2v[co] + o1v[co];
            float* row = out + ((size_t)(b * COUTC + co) * HH + h) * WW;
#pragma unroll
            for (int nf = 0; nf < 4; nf++) {
                int px = wn * 32 + nf * 8 + 2 * (lid & 3);
                float2 v;
                v.x = fmaxf(acc[mt][nf][half * 2 + 0] + sh, 0.f);
                v.y = fmaxf(acc[mt][nf][half * 2 + 1] + sh, 0.f);
                *(float2*)(row + px) = v;
            }
        }
    }
}

// ---------------- launch ----------------
extern "C" void kernel_launch(void* const* d_in, const int* in_sizes, int n_in,
                              void* d_out, int out_size)
{
    const float* x   = (const float*)d_in[0];
    const float* w_l = (const float*)d_in[1];
    const float* s_l = (const float*)d_in[2];
    const float* o_l = (const float*)d_in[3];
    const float* w_r = (const float*)d_in[4];
    const float* s_r = (const float*)d_in[5];
    const float* o_r = (const float*)d_in[6];
    const float* w_t = (const float*)d_in[7];
    const float* s_t = (const float*)d_in[8];
    const float* o_t = (const float*)d_in[9];
    const float* w_b = (const float*)d_in[10];
    const float* s_b = (const float*)d_in[11];
    const float* o_b = (const float*)d_in[12];
    const float* w2  = (const float*)d_in[13];
    const float* s2  = (const float*)d_in[14];
    const float* o2  = (const float*)d_in[15];
    const float* w1  = (const float*)d_in[16];
    const float* s1  = (const float*)d_in[17];
    const float* o1  = (const float*)d_in[18];
    float* out = (float*)d_out;

    cudaFuncSetAttribute(k_conv_branch, cudaFuncAttributeMaxDynamicSharedMemorySize, SMEM_BYTES);
    cudaFuncSetAttribute(k_conv_out,    cudaFuncAttributeMaxDynamicSharedMemorySize, SMEM_BYTES);

    k_repack_br<<<576, 256>>>(w_l, s_l, 0);
    k_repack_br<<<576, 256>>>(w_r, s_r, 1);
    k_repack_br<<<576, 256>>>(w_t, s_t, 2);
    k_repack_br<<<576, 256>>>(w_b, s_b, 3);
    k_repack_w2<<<576, 256>>>(w2, s2);
    k_repack_w1<<<128, 256>>>(w1, s1);

    dim3 g1(HH, BN, 4);
    k_conv_branch<<<g1, 512, SMEM_BYTES>>>(x, o_l, o_r, o_t, o_b);
    k_scan_w<<<BN * CMID, 128>>>();
    k_scan_h<<<BN * CMID, 128>>>();
    dim3 g3(HH, BN, 2);
    k_conv_out<<<g3, 512, SMEM_BYTES>>>(x, o2, o1, out);
}

// round 7
// speedup vs baseline: 2.4663x; 1.1740x over previous
#include <cuda_runtime.h>
#include <cuda_bf16.h>
#include <cstdint>
#include <math.h>

#define BN    8
#define CINC  256
#define CMID  128
#define COUTC 256
#define HH    128
#define WW    128

typedef uint32_t u32;

// ---------------- scratch (static __device__ — allocation-free) ----------------
__device__ float g_y[4][BN * CMID * HH * WW];  // branch conv outputs (post-relu)
__device__ float g_S[BN * CMID * HH * WW];     // sum of 4 scanned branches
// bf16-split weights: branch [tap=br*9+kh*3+kw][co=128][cipair]
__device__ __align__(16) __nv_bfloat162 g_wAh[36 * 128 * 128];
__device__ __align__(16) __nv_bfloat162 g_wAl[36 * 128 * 128];
__device__ __align__(16) __nv_bfloat162 g_w2h[9 * 256 * 64];   // [t][co=256][cipair=64]
__device__ __align__(16) __nv_bfloat162 g_w2l[9 * 256 * 64];
__device__ __align__(16) __nv_bfloat162 g_w1h[256 * 128];      // [co=256][cipair=128]
__device__ __align__(16) __nv_bfloat162 g_w1l[256 * 128];

// ---------------- helpers ----------------
__device__ __forceinline__ u32 smem_u32(const void* p) {
    u32 a;
    asm("{ .reg .u64 t; cvta.to.shared.u64 t, %1; cvt.u32.u64 %0, t; }" : "=r"(a) : "l"(p));
    return a;
}

// XOR swizzle: byte bits [6:4] ^= bits [9:7]  (rows are 128B)
#define SWZ(off) ((off) ^ (((off) >> 3) & 0x70))

__device__ __forceinline__ void ldm_x4(u32* r, u32 addr) {
    asm volatile("ldmatrix.sync.aligned.m8n8.x4.shared.b16 {%0,%1,%2,%3}, [%4];"
                 : "=r"(r[0]), "=r"(r[1]), "=r"(r[2]), "=r"(r[3]) : "r"(addr));
}
__device__ __forceinline__ void mma16816(float* d, const u32* a, const u32* b) {
    asm volatile("mma.sync.aligned.m16n8k16.row.col.f32.bf16.bf16.f32 "
                 "{%0,%1,%2,%3}, {%4,%5,%6,%7}, {%8,%9}, {%0,%1,%2,%3};"
                 : "+f"(d[0]), "+f"(d[1]), "+f"(d[2]), "+f"(d[3])
                 : "r"(a[0]), "r"(a[1]), "r"(a[2]), "r"(a[3]), "r"(b[0]), "r"(b[1]));
}
__device__ __forceinline__ void cpa16(u32 d, const void* s) {
    asm volatile("cp.async.cg.shared.global [%0], [%1], 16;" :: "r"(d), "l"(s));
}
#define CPA_COMMIT() asm volatile("cp.async.commit_group;" ::: "memory")
#define CPA_WAIT0()  asm volatile("cp.async.wait_group 0;" ::: "memory")

// smem layout: two A buffers (hi+lo 16KB each), one extended B tile (132 rows)
#define OFF_A0 0
#define OFF_A1 32768
#define OFF_BH 65536
#define OFF_BL 82944
#define SMEM_BYTES (82944 + 16896)

__device__ __forceinline__ void split2(float v0, float v1, u32 sb, u32 off) {
    __nv_bfloat16 h0 = __float2bfloat16(v0), h1 = __float2bfloat16(v1);
    __nv_bfloat16 l0 = __float2bfloat16(v0 - __bfloat162float(h0));
    __nv_bfloat16 l1 = __float2bfloat16(v1 - __bfloat162float(h1));
    u32 sw = SWZ(off);
    u32 hv, lv;
    asm("mov.b32 %0, {%1, %2};" : "=r"(hv) : "h"(*(unsigned short*)&h0), "h"(*(unsigned short*)&h1));
    asm("mov.b32 %0, {%1, %2};" : "=r"(lv) : "h"(*(unsigned short*)&l0), "h"(*(unsigned short*)&l1));
    asm volatile("st.shared.b32 [%0], %1;" :: "r"(sb + OFF_BH + sw), "r"(hv) : "memory");
    asm volatile("st.shared.b32 [%0], %1;" :: "r"(sb + OFF_BL + sw), "r"(lv) : "memory");
}

// ---------------- weight repack (+BN scale fold, bf16 hi/lo split) ----------------
__global__ void k_repack_br(const float* __restrict__ w, const float* __restrict__ s, int br)
{
    int slot = blockIdx.x * 256 + threadIdx.x;       // 9*128*128
    if (slot >= 147456) return;
    int pair = slot & 127;
    int co   = (slot >> 7) & 127;
    int t    = slot >> 14;
    int kh = t / 3, kw = t % 3;
    int ci = pair * 2;
    float sc = s[co];
    float v0 = w[((co * CINC + ci)     * 3 + kh) * 3 + kw] * sc;
    float v1 = w[((co * CINC + ci + 1) * 3 + kh) * 3 + kw] * sc;
    __nv_bfloat16 h0 = __float2bfloat16(v0), h1 = __float2bfloat16(v1);
    __nv_bfloat16 l0 = __float2bfloat16(v0 - __bfloat162float(h0));
    __nv_bfloat16 l1 = __float2bfloat16(v1 - __bfloat162float(h1));
    int idx = ((br * 9 + t) * 128 + co) * 128 + pair;
    g_wAh[idx] = __halves2bfloat162(h0, h1);
    g_wAl[idx] = __halves2bfloat162(l0, l1);
}

__global__ void k_repack_w2(const float* __restrict__ w, const float* __restrict__ s)
{
    int slot = blockIdx.x * 256 + threadIdx.x;       // 9*256*64
    if (slot >= 147456) return;
    int pair = slot & 63;
    int co   = (slot >> 6) & 255;
    int t    = slot >> 14;
    int kh = t / 3, kw = t % 3;
    int ci = pair * 2;
    float sc = s[co];
    float v0 = w[((co * CMID + ci)     * 3 + kh) * 3 + kw] * sc;
    float v1 = w[((co * CMID + ci + 1) * 3 + kh) * 3 + kw] * sc;
    __nv_bfloat16 h0 = __float2bfloat16(v0), h1 = __float2bfloat16(v1);
    __nv_bfloat16 l0 = __float2bfloat16(v0 - __bfloat162float(h0));
    __nv_bfloat16 l1 = __float2bfloat16(v1 - __bfloat162float(h1));
    int idx = (t * 256 + co) * 64 + pair;
    g_w2h[idx] = __halves2bfloat162(h0, h1);
    g_w2l[idx] = __halves2bfloat162(l0, l1);
}

__global__ void k_repack_w1(const float* __restrict__ w, const float* __restrict__ s)
{
    int slot = blockIdx.x * 256 + threadIdx.x;       // 256*128
    if (slot >= 32768) return;
    int pair = slot & 127;
    int co   = slot >> 7;
    int ci = pair * 2;
    float sc = s[co];
    float v0 = w[co * CINC + ci]     * sc;
    float v1 = w[co * CINC + ci + 1] * sc;
    __nv_bfloat16 h0 = __float2bfloat16(v0), h1 = __float2bfloat16(v1);
    __nv_bfloat16 l0 = __float2bfloat16(v0 - __bfloat162float(h0));
    __nv_bfloat16 l1 = __float2bfloat16(v1 - __bfloat162float(h1));
    g_w1h[co * 128 + pair] = __halves2bfloat162(h0, h1);
    g_w1l[co * 128 + pair] = __halves2bfloat162(l0, l1);
}

// ---------------- A tile via cp.async (16B chunks, source rows match tile rows) ----------------
__device__ __forceinline__ void build_A_async(u32 sb, u32 offA, int tid,
                                              const __nv_bfloat162* __restrict__ wh,
                                              const __nv_bfloat162* __restrict__ wl,
                                              int rsp /*pairs*/, int pair0)
{
#pragma unroll
    for (int q = 0; q < 2; q++) {
        int slot = tid + 512 * q;            // 1024 x 16B = 16KB per half
        int co = slot >> 3;
        int c  = slot & 7;
        u32 d = SWZ((u32)(co * 128 + c * 16));
        const char* sh = (const char*)(wh + (size_t)co * rsp + pair0) + c * 16;
        const char* sl = (const char*)(wl + (size_t)co * rsp + pair0) + c * 16;
        cpa16(sb + offA + d, sh);
        cpa16(sb + offA + 16384 + d, sl);
    }
}

// ---------------- extended B tile: 132 rows (row r = source px r-1) x 64 ci ----------------
__device__ __forceinline__ void build_B_ext(u32 sb, int tid, const float* __restrict__ src,
                                            int nchan, int b, int c0, int srow)
{
    const size_t HW = (size_t)HH * WW;
    bool rowok = (srow >= 0) && (srow < HH);
    const float* base = src + ((size_t)(b * nchan + c0) * HH + (rowok ? srow : 0)) * WW;
    int p  = tid & 127;                      // coalesced pixel index
    int gp = tid >> 7;                       // 0..3 channel group
    int spx = p - 1;
    bool okm = rowok && (spx >= 0);
    const float* bp = base + spx;
#pragma unroll
    for (int q = 0; q < 8; q++) {
        int cil = gp * 16 + 2 * q;
        float v0 = okm ? bp[(size_t)cil * HW] : 0.f;
        float v1 = okm ? bp[(size_t)(cil + 1) * HW] : 0.f;
        split2(v0, v1, sb, (u32)(p * 128 + 2 * cil));
    }
    if (tid < 128) {                         // tail rows 128..131 (src px 127..130)
        int r  = 128 + (tid >> 5);
        int pc = tid & 31;
        int cil = 2 * pc;
        int sp2 = r - 1;
        bool ok = rowok && (sp2 < WW);
        float v0 = ok ? base[(size_t)cil * HW + sp2] : 0.f;
        float v1 = ok ? base[(size_t)(cil + 1) * HW + sp2] : 0.f;
        split2(v0, v1, sb, (u32)(r * 128 + 2 * cil));
    }
}

// ---------------- mma over one 64-k chunk; B rows shifted by kw ----------------
__device__ __forceinline__ void mma_chunk(u32 sb, u32 offA, int kw,
                                          int wm, int wn, int lid, float acc[2][4][4])
{
    const u32 lrow  = (u32)(lid & 15) * 128;
    const u32 lkh   = (u32)((lid >> 4) << 4);
    const u32 brow0 = (u32)kw * 128 + lrow;
#pragma unroll
    for (int ks = 0; ks < 4; ks++) {
        const u32 kb = (u32)(ks * 32) + lkh;
        u32 ah[2][4], al[2][4], bh[2][4], bl[2][4];
#pragma unroll
        for (int mt = 0; mt < 2; mt++) {
            u32 off = SWZ((u32)((wm * 32 + mt * 16) * 128) + lrow + kb);
            ldm_x4(ah[mt], sb + offA + off);
            ldm_x4(al[mt], sb + offA + 16384 + off);
        }
#pragma unroll
        for (int bt = 0; bt < 2; bt++) {
            u32 off = SWZ((u32)((wn * 32 + bt * 16) * 128) + brow0 + kb);
            ldm_x4(bh[bt], sb + OFF_BH + off);
            ldm_x4(bl[bt], sb + OFF_BL + off);
        }
#pragma unroll
        for (int mt = 0; mt < 2; mt++)
#pragma unroll
            for (int bt = 0; bt < 2; bt++)
#pragma unroll
                for (int j = 0; j < 2; j++) {
                    u32 BH2[2] = { bh[bt][j], bh[bt][j + 2] };
                    u32 BL2[2] = { bl[bt][j], bl[bt][j + 2] };
                    float* d = acc[mt][bt * 2 + j];
                    mma16816(d, ah[mt], BH2);
                    mma16816(d, ah[mt], BL2);
                    mma16816(d, al[mt], BH2);
                }
    }
}

// ---------------- fused 4-branch 3x3 conv + BN + relu (HMMA, pipelined) ----------------
// grid = (H=128, B=8, br=4), 512 threads; block tile 128co x 128px
__global__ __launch_bounds__(512, 1)
void k_conv_branch(const float* __restrict__ x,
                   const float* __restrict__ ob0, const float* __restrict__ ob1,
                   const float* __restrict__ ob2, const float* __restrict__ ob3)
{
    extern __shared__ char smem_raw[];
    u32 sb = smem_u32(smem_raw);
    const int h  = blockIdx.x;
    const int b  = blockIdx.y;
    const int br = blockIdx.z;
    const int tid = threadIdx.x;
    const int wid = tid >> 5, lid = tid & 31;
    const int wm = wid >> 2, wn = wid & 3;

    float acc[2][4][4];
#pragma unroll
    for (int i = 0; i < 2; i++)
#pragma unroll
        for (int j = 0; j < 4; j++)
#pragma unroll
            for (int k = 0; k < 4; k++) acc[i][j][k] = 0.f;

    for (int kh = 0; kh < 3; kh++) {
        int srow = h + kh - 1;
        for (int c0 = 0; c0 < CINC; c0 += 64) {
            __syncthreads();                 // B + A bufs free
            {
                size_t t0 = (size_t)(br * 9 + kh * 3) * 128 * 128;
                build_A_async(sb, OFF_A0, tid, g_wAh + t0, g_wAl + t0, 128, c0 >> 1);
                CPA_COMMIT();
            }
            build_B_ext(sb, tid, x, CINC, b, c0, srow);   // overlaps A0 fetch
            for (int kw = 0; kw < 3; kw++) {
                CPA_WAIT0();
                __syncthreads();
                if (kw < 2) {                // prefetch next A under this kw's MMAs
                    size_t tn = (size_t)(br * 9 + kh * 3 + kw + 1) * 128 * 128;
                    build_A_async(sb, ((kw + 1) & 1) ? OFF_A1 : OFF_A0, tid,
                                  g_wAh + tn, g_wAl + tn, 128, c0 >> 1);
                    CPA_COMMIT();
                }
                mma_chunk(sb, (kw & 1) ? OFF_A1 : OFF_A0, kw, wm, wn, lid, acc);
            }
        }
    }

    const float* ob = (br == 0) ? ob0 : (br == 1) ? ob1 : (br == 2) ? ob2 : ob3;
    float* yb = g_y[br];
#pragma unroll
    for (int mt = 0; mt < 2; mt++) {
        int r0 = wm * 32 + mt * 16 + (lid >> 2);
#pragma unroll
        for (int half = 0; half < 2; half++) {
            int co = r0 + half * 8;
            float sh = ob[co];
            float* row = yb + ((size_t)(b * CMID + co) * HH + h) * WW;
#pragma unroll
            for (int nf = 0; nf < 4; nf++) {
                int px = wn * 32 + nf * 8 + 2 * (lid & 3);
                float2 v;
                v.x = fmaxf(acc[mt][nf][half * 2 + 0] + sh, 0.f);
                v.y = fmaxf(acc[mt][nf][half * 2 + 1] + sh, 0.f);
                *(float2*)(row + px) = v;
            }
        }
    }
}

// ---------------- scans along W ----------------
__global__ void k_scan_w()
{
    int bc = blockIdx.x;
    int h  = threadIdx.x;
    const float* yl = g_y[0] + (size_t)bc * (HH * WW) + h * WW;
    const float* yr = g_y[1] + (size_t)bc * (HH * WW) + h * WW;
    float* Sp = g_S + (size_t)bc * (HH * WW) + h * WW;
    float m = -INFINITY;
    for (int w = WW - 1; w >= 0; --w) { m = fmaxf(m, yl[w]); Sp[w] = m; }
    m = -INFINITY;
    for (int w = 0; w < WW; ++w)    { m = fmaxf(m, yr[w]); Sp[w] += m; }
}

// ---------------- scans along H ----------------
__global__ void k_scan_h()
{
    int bc = blockIdx.x;
    int w  = threadIdx.x;
    const float* yt = g_y[2] + (size_t)bc * (HH * WW) + w;
    const float* yv = g_y[3] + (size_t)bc * (HH * WW) + w;
    float* Sp = g_S + (size_t)bc * (HH * WW) + w;
    float m = -INFINITY;
    for (int hq = HH - 1; hq >= 0; --hq) { m = fmaxf(m, yt[hq * WW]); Sp[hq * WW] += m; }
    m = -INFINITY;
    for (int hq = 0; hq < HH; ++hq)      { m = fmaxf(m, yv[hq * WW]); Sp[hq * WW] += m; }
}

// ---------------- conv2 3x3 over S + 1x1 skip over x + relu -> out (HMMA, pipelined) ----------------
// grid = (H=128, B=8, ct=2), 512 threads
__global__ __launch_bounds__(512, 1)
void k_conv_out(const float* __restrict__ x,
                const float* __restrict__ o2v, const float* __restrict__ o1v,
                float* __restrict__ out)
{
    extern __shared__ char smem_raw[];
    u32 sb = smem_u32(smem_raw);
    const int h  = blockIdx.x;
    const int b  = blockIdx.y;
    const int ct = blockIdx.z;
    const int tid = threadIdx.x;
    const int wid = tid >> 5, lid = tid & 31;
    const int wm = wid >> 2, wn = wid & 3;

    float acc[2][4][4];
#pragma unroll
    for (int i = 0; i < 2; i++)
#pragma unroll
        for (int j = 0; j < 4; j++)
#pragma unroll
            for (int k = 0; k < 4; k++) acc[i][j][k] = 0.f;

    // phase 1: 3x3 conv over g_S (128 ci)
    for (int kh = 0; kh < 3; kh++) {
        int srow = h + kh - 1;
        for (int c0 = 0; c0 < CMID; c0 += 64) {
            __syncthreads();
            {
                size_t t0 = ((size_t)(kh * 3) * 256 + ct * 128) * 64;
                build_A_async(sb, OFF_A0, tid, g_w2h + t0, g_w2l + t0, 64, c0 >> 1);
                CPA_COMMIT();
            }
            build_B_ext(sb, tid, g_S, CMID, b, c0, srow);
            for (int kw = 0; kw < 3; kw++) {
                CPA_WAIT0();
                __syncthreads();
                if (kw < 2) {
                    size_t tn = ((size_t)(kh * 3 + kw + 1) * 256 + ct * 128) * 64;
                    build_A_async(sb, ((kw + 1) & 1) ? OFF_A1 : OFF_A0, tid,
                                  g_w2h + tn, g_w2l + tn, 64, c0 >> 1);
                    CPA_COMMIT();
                }
                mma_chunk(sb, (kw & 1) ? OFF_A1 : OFF_A0, kw, wm, wn, lid, acc);
            }
        }
    }
    // phase 2: 1x1 skip over x (256 ci); kw=1 row offset reads unshifted pixels
    {
        const __nv_bfloat162* wh = g_w1h + (size_t)(ct * 128) * 128;
        const __nv_bfloat162* wl = g_w1l + (size_t)(ct * 128) * 128;
        for (int c0 = 0; c0 < CINC; c0 += 64) {
            __syncthreads();
            build_A_async(sb, OFF_A0, tid, wh, wl, 128, c0 >> 1);
            CPA_COMMIT();
            build_B_ext(sb, tid, x, CINC, b, c0, h);
            CPA_WAIT0();
            __syncthreads();
            mma_chunk(sb, OFF_A0, 1, wm, wn, lid, acc);
        }
    }

#pragma unroll
    for (int mt = 0; mt < 2; mt++) {
        int r0 = wm * 32 + mt * 16 + (lid >> 2);
#pragma unroll
        for (int half = 0; half < 2; half++) {
            int co = ct * 128 + r0 + half * 8;
            float sh = o2v[co] + o1v[co];
            float* row = out + ((size_t)(b * COUTC + co) * HH + h) * WW;
#pragma unroll
            for (int nf = 0; nf < 4; nf++) {
                int px = wn * 32 + nf * 8 + 2 * (lid & 3);
                float2 v;
                v.x = fmaxf(acc[mt][nf][half * 2 + 0] + sh, 0.f);
                v.y = fmaxf(acc[mt][nf][half * 2 + 1] + sh, 0.f);
                *(float2*)(row + px) = v;
            }
        }
    }
}

// ---------------- launch ----------------
extern "C" void kernel_launch(void* const* d_in, const int* in_sizes, int n_in,
                              void* d_out, int out_size)
{
    const float* x   = (const float*)d_in[0];
    const float* w_l = (const float*)d_in[1];
    const float* s_l = (const float*)d_in[2];
    const float* o_l = (const float*)d_in[3];
    const float* w_r = (const float*)d_in[4];
    const float* s_r = (const float*)d_in[5];
    const float* o_r = (const float*)d_in[6];
    const float* w_t = (const float*)d_in[7];
    const float* s_t = (const float*)d_in[8];
    const float* o_t = (const float*)d_in[9];
    const float* w_b = (const float*)d_in[10];
    const float* s_b = (const float*)d_in[11];
    const float* o_b = (const float*)d_in[12];
    const float* w2  = (const float*)d_in[13];
    const float* s2  = (const float*)d_in[14];
    const float* o2  = (const float*)d_in[15];
    const float* w1  = (const float*)d_in[16];
    const float* s1  = (const float*)d_in[17];
    const float* o1  = (const float*)d_in[18];
    float* out = (float*)d_out;

    cudaFuncSetAttribute(k_conv_branch, cudaFuncAttributeMaxDynamicSharedMemorySize, SMEM_BYTES);
    cudaFuncSetAttribute(k_conv_out,    cudaFuncAttributeMaxDynamicSharedMemorySize, SMEM_BYTES);

    k_repack_br<<<576, 256>>>(w_l, s_l, 0);
    k_repack_br<<<576, 256>>>(w_r, s_r, 1);
    k_repack_br<<<576, 256>>>(w_t, s_t, 2);
    k_repack_br<<<576, 256>>>(w_b, s_b, 3);
    k_repack_w2<<<576, 256>>>(w2, s2);
    k_repack_w1<<<128, 256>>>(w1, s1);

    dim3 g1(HH, BN, 4);
    k_conv_branch<<<g1, 512, SMEM_BYTES>>>(x, o_l, o_r, o_t, o_b);
    k_scan_w<<<BN * CMID, 128>>>();
    k_scan_h<<<BN * CMID, 128>>>();
    dim3 g3(HH, BN, 2);
    k_conv_out<<<g3, 512, SMEM_BYTES>>>(x, o2, o1, out);
}

// round 8
// speedup vs baseline: 3.4067x; 1.3813x over previous
#include <cuda_runtime.h>
#include <cuda_bf16.h>
#include <cstdint>
#include <math.h>

#define BN    8
#define CINC  256
#define CMID  128
#define COUTC 256
#define HH    128
#define WW    128

typedef uint32_t u32;

// ---------------- scratch (static __device__ — allocation-free) ----------------
__device__ float g_y[4][BN * CMID * HH * WW];  // branch conv outputs (post-relu)
__device__ float g_S[BN * CMID * HH * WW];     // sum of 4 scanned branches
// bf16-split weights: branch [tap=br*9+kh*3+kw][co=128][cipair]
__device__ __align__(16) __nv_bfloat162 g_wAh[36 * 128 * 128];
__device__ __align__(16) __nv_bfloat162 g_wAl[36 * 128 * 128];
__device__ __align__(16) __nv_bfloat162 g_w2h[9 * 256 * 64];   // [t][co=256][cipair=64]
__device__ __align__(16) __nv_bfloat162 g_w2l[9 * 256 * 64];
__device__ __align__(16) __nv_bfloat162 g_w1h[256 * 128];      // [co=256][cipair=128]
__device__ __align__(16) __nv_bfloat162 g_w1l[256 * 128];

// ---------------- helpers ----------------
__device__ __forceinline__ u32 smem_u32(const void* p) {
    u32 a;
    asm("{ .reg .u64 t; cvta.to.shared.u64 t, %1; cvt.u32.u64 %0, t; }" : "=r"(a) : "l"(p));
    return a;
}

// XOR swizzle: byte bits [6:4] ^= bits [9:7]  (rows are 128B)
#define SWZ(off) ((off) ^ (((off) >> 3) & 0x70))

__device__ __forceinline__ void ldm_x4(u32* r, u32 addr) {
    asm volatile("ldmatrix.sync.aligned.m8n8.x4.shared.b16 {%0,%1,%2,%3}, [%4];"
                 : "=r"(r[0]), "=r"(r[1]), "=r"(r[2]), "=r"(r[3]) : "r"(addr));
}
__device__ __forceinline__ void mma16816(float* d, const u32* a, const u32* b) {
    asm volatile("mma.sync.aligned.m16n8k16.row.col.f32.bf16.bf16.f32 "
                 "{%0,%1,%2,%3}, {%4,%5,%6,%7}, {%8,%9}, {%0,%1,%2,%3};"
                 : "+f"(d[0]), "+f"(d[1]), "+f"(d[2]), "+f"(d[3])
                 : "r"(a[0]), "r"(a[1]), "r"(a[2]), "r"(a[3]), "r"(b[0]), "r"(b[1]));
}
__device__ __forceinline__ void cpa16(u32 d, const void* s) {
    asm volatile("cp.async.cg.shared.global [%0], [%1], 16;" :: "r"(d), "l"(s));
}
#define CPA_COMMIT() asm volatile("cp.async.commit_group;" ::: "memory")
#define CPA_WAIT0()  asm volatile("cp.async.wait_group 0;" ::: "memory")

// smem layout: two A buffers (hi+lo 16KB each), two extended B buffers (132 rows, hi+lo)
#define BSZ    16896                    // 132 * 128 bytes
#define OFF_A0 0
#define OFF_A1 32768
#define OFF_B0 65536
#define OFF_B1 (65536 + 2 * BSZ)        // 99328
#define SMEM_BYTES (OFF_B1 + 2 * BSZ)   // 133120

__device__ __forceinline__ void split2(float v0, float v1, u32 sb, u32 offB, u32 off) {
    __nv_bfloat16 h0 = __float2bfloat16(v0), h1 = __float2bfloat16(v1);
    __nv_bfloat16 l0 = __float2bfloat16(v0 - __bfloat162float(h0));
    __nv_bfloat16 l1 = __float2bfloat16(v1 - __bfloat162float(h1));
    u32 sw = SWZ(off);
    u32 hv, lv;
    asm("mov.b32 %0, {%1, %2};" : "=r"(hv) : "h"(*(unsigned short*)&h0), "h"(*(unsigned short*)&h1));
    asm("mov.b32 %0, {%1, %2};" : "=r"(lv) : "h"(*(unsigned short*)&l0), "h"(*(unsigned short*)&l1));
    asm volatile("st.shared.b32 [%0], %1;" :: "r"(sb + offB + sw), "r"(hv) : "memory");
    asm volatile("st.shared.b32 [%0], %1;" :: "r"(sb + offB + BSZ + sw), "r"(lv) : "memory");
}

// ---------------- weight repack (+BN scale fold, bf16 hi/lo split) ----------------
__global__ void k_repack_br(const float* __restrict__ w, const float* __restrict__ s, int br)
{
    int slot = blockIdx.x * 256 + threadIdx.x;       // 9*128*128
    if (slot >= 147456) return;
    int pair = slot & 127;
    int co   = (slot >> 7) & 127;
    int t    = slot >> 14;
    int kh = t / 3, kw = t % 3;
    int ci = pair * 2;
    float sc = s[co];
    float v0 = w[((co * CINC + ci)     * 3 + kh) * 3 + kw] * sc;
    float v1 = w[((co * CINC + ci + 1) * 3 + kh) * 3 + kw] * sc;
    __nv_bfloat16 h0 = __float2bfloat16(v0), h1 = __float2bfloat16(v1);
    __nv_bfloat16 l0 = __float2bfloat16(v0 - __bfloat162float(h0));
    __nv_bfloat16 l1 = __float2bfloat16(v1 - __bfloat162float(h1));
    int idx = ((br * 9 + t) * 128 + co) * 128 + pair;
    g_wAh[idx] = __halves2bfloat162(h0, h1);
    g_wAl[idx] = __halves2bfloat162(l0, l1);
}

__global__ void k_repack_w2(const float* __restrict__ w, const float* __restrict__ s)
{
    int slot = blockIdx.x * 256 + threadIdx.x;       // 9*256*64
    if (slot >= 147456) return;
    int pair = slot & 63;
    int co   = (slot >> 6) & 255;
    int t    = slot >> 14;
    int kh = t / 3, kw = t % 3;
    int ci = pair * 2;
    float sc = s[co];
    float v0 = w[((co * CMID + ci)     * 3 + kh) * 3 + kw] * sc;
    float v1 = w[((co * CMID + ci + 1) * 3 + kh) * 3 + kw] * sc;
    __nv_bfloat16 h0 = __float2bfloat16(v0), h1 = __float2bfloat16(v1);
    __nv_bfloat16 l0 = __float2bfloat16(v0 - __bfloat162float(h0));
    __nv_bfloat16 l1 = __float2bfloat16(v1 - __bfloat162float(h1));
    int idx = (t * 256 + co) * 64 + pair;
    g_w2h[idx] = __halves2bfloat162(h0, h1);
    g_w2l[idx] = __halves2bfloat162(l0, l1);
}

__global__ void k_repack_w1(const float* __restrict__ w, const float* __restrict__ s)
{
    int slot = blockIdx.x * 256 + threadIdx.x;       // 256*128
    if (slot >= 32768) return;
    int pair = slot & 127;
    int co   = slot >> 7;
    int ci = pair * 2;
    float sc = s[co];
    float v0 = w[co * CINC + ci]     * sc;
    float v1 = w[co * CINC + ci + 1] * sc;
    __nv_bfloat16 h0 = __float2bfloat16(v0), h1 = __float2bfloat16(v1);
    __nv_bfloat16 l0 = __float2bfloat16(v0 - __bfloat162float(h0));
    __nv_bfloat16 l1 = __float2bfloat16(v1 - __bfloat162float(h1));
    g_w1h[co * 128 + pair] = __halves2bfloat162(h0, h1);
    g_w1l[co * 128 + pair] = __halves2bfloat162(l0, l1);
}

// ---------------- A tile via cp.async (16B chunks, source rows match tile rows) ----------------
__device__ __forceinline__ void build_A_async(u32 sb, u32 offA, int tid,
                                              const __nv_bfloat162* __restrict__ wh,
                                              const __nv_bfloat162* __restrict__ wl,
                                              int rsp /*pairs*/, int pair0)
{
#pragma unroll
    for (int q = 0; q < 2; q++) {
        int slot = tid + 512 * q;            // 1024 x 16B = 16KB per half
        int co = slot >> 3;
        int c  = slot & 7;
        u32 d = SWZ((u32)(co * 128 + c * 16));
        const char* sh = (const char*)(wh + (size_t)co * rsp + pair0) + c * 16;
        const char* sl = (const char*)(wl + (size_t)co * rsp + pair0) + c * 16;
        cpa16(sb + offA + d, sh);
        cpa16(sb + offA + 16384 + d, sl);
    }
}

// ---------------- B staged through registers ----------------
struct BReg { float m[16]; float t0, t1; };

__device__ __forceinline__ void ldg_B(BReg& r, int tid, const float* __restrict__ src,
                                      int nchan, int b, int c0, int srow)
{
    const size_t HW = (size_t)HH * WW;
    bool rowok = (srow >= 0) && (srow < HH);
    const float* base = src + ((size_t)(b * nchan + c0) * HH + (rowok ? srow : 0)) * WW;
    int p  = tid & 127;
    int gp = tid >> 7;
    int spx = p - 1;
    bool okm = rowok && (spx >= 0);
    const float* bp = base + spx;
#pragma unroll
    for (int q = 0; q < 8; q++) {
        int cil = gp * 16 + 2 * q;
        r.m[2 * q]     = okm ? bp[(size_t)cil * HW] : 0.f;
        r.m[2 * q + 1] = okm ? bp[(size_t)(cil + 1) * HW] : 0.f;
    }
    if (tid < 128) {
        int rr = 128 + (tid >> 5);
        int pc = tid & 31;
        int cil = 2 * pc;
        int sp2 = rr - 1;
        bool ok = rowok && (sp2 < WW);
        r.t0 = ok ? base[(size_t)cil * HW + sp2] : 0.f;
        r.t1 = ok ? base[(size_t)(cil + 1) * HW + sp2] : 0.f;
    }
}

__device__ __forceinline__ void st_B(const BReg& r, u32 sb, u32 offB, int tid)
{
    int p  = tid & 127;
    int gp = tid >> 7;
#pragma unroll
    for (int q = 0; q < 8; q++) {
        int cil = gp * 16 + 2 * q;
        split2(r.m[2 * q], r.m[2 * q + 1], sb, offB, (u32)(p * 128 + 2 * cil));
    }
    if (tid < 128) {
        int rr = 128 + (tid >> 5);
        int pc = tid & 31;
        split2(r.t0, r.t1, sb, offB, (u32)(rr * 128 + 2 * pc * 2));
    }
}

// ---------------- mma over one 64-k chunk; B rows shifted by kw ----------------
__device__ __forceinline__ void mma_chunk(u32 sb, u32 offA, u32 offB, int kw,
                                          int wm, int wn, int lid, float acc[2][4][4])
{
    const u32 lrow  = (u32)(lid & 15) * 128;
    const u32 lkh   = (u32)((lid >> 4) << 4);
    const u32 brow0 = (u32)kw * 128 + lrow;
#pragma unroll
    for (int ks = 0; ks < 4; ks++) {
        const u32 kb = (u32)(ks * 32) + lkh;
        u32 ah[2][4], al[2][4], bh[2][4], bl[2][4];
#pragma unroll
        for (int mt = 0; mt < 2; mt++) {
            u32 off = SWZ((u32)((wm * 32 + mt * 16) * 128) + lrow + kb);
            ldm_x4(ah[mt], sb + offA + off);
            ldm_x4(al[mt], sb + offA + 16384 + off);
        }
#pragma unroll
        for (int bt = 0; bt < 2; bt++) {
            u32 off = SWZ((u32)((wn * 32 + bt * 16) * 128) + brow0 + kb);
            ldm_x4(bh[bt], sb + offB + off);
            ldm_x4(bl[bt], sb + offB + BSZ + off);
        }
#pragma unroll
        for (int mt = 0; mt < 2; mt++)
#pragma unroll
            for (int bt = 0; bt < 2; bt++)
#pragma unroll
                for (int j = 0; j < 2; j++) {
                    u32 BH2[2] = { bh[bt][j], bh[bt][j + 2] };
                    u32 BL2[2] = { bl[bt][j], bl[bt][j + 2] };
                    float* d = acc[mt][bt * 2 + j];
                    mma16816(d, ah[mt], BH2);
                    mma16816(d, ah[mt], BL2);
                    mma16816(d, al[mt], BH2);
                }
    }
}

// ---------------- fused 4-branch 3x3 conv + BN + relu (HMMA, B reg-pipelined) ----------------
// grid = (H=128, B=8, br=4), 512 threads; block tile 128co x 128px
// chunks: 12 = kh(3) x c0(4); steps: 36 = chunks x kw(3)
__global__ __launch_bounds__(512, 1)
void k_conv_branch(const float* __restrict__ x,
                   const float* __restrict__ ob0, const float* __restrict__ ob1,
                   const float* __restrict__ ob2, const float* __restrict__ ob3)
{
    extern __shared__ char smem_raw[];
    u32 sb = smem_u32(smem_raw);
    const int h  = blockIdx.x;
    const int b  = blockIdx.y;
    const int br = blockIdx.z;
    const int tid = threadIdx.x;
    const int wid = tid >> 5, lid = tid & 31;
    const int wm = wid >> 2, wn = wid & 3;

    float acc[2][4][4];
#pragma unroll
    for (int i = 0; i < 2; i++)
#pragma unroll
        for (int j = 0; j < 4; j++)
#pragma unroll
            for (int k = 0; k < 4; k++) acc[i][j][k] = 0.f;

    BReg breg;
    ldg_B(breg, tid, x, CINC, b, 0, h - 1);          // chunk 0: kh=0, c0=0
    {
        size_t t0 = (size_t)(br * 9) * 16384;        // step 0: kh=0,kw=0
        build_A_async(sb, OFF_A0, tid, g_wAh + t0, g_wAl + t0, 128, 0);
        CPA_COMMIT();
    }

    for (int ch = 0; ch < 12; ch++) {
        u32 offB = (ch & 1) ? OFF_B1 : OFF_B0;
        st_B(breg, sb, offB, tid);
        __syncthreads();
        if (ch + 1 < 12) {
            int kh2 = (ch + 1) >> 2, c02 = ((ch + 1) & 3) * 64;
            ldg_B(breg, tid, x, CINC, b, c02, h + kh2 - 1);    // drains under MMAs
        }
#pragma unroll
        for (int kw = 0; kw < 3; kw++) {
            int step = ch * 3 + kw;
            CPA_WAIT0();
            __syncthreads();
            if (step + 1 < 36) {
                int s2 = step + 1, ch2 = s2 / 3, kw2 = s2 - ch2 * 3;
                int kh2 = ch2 >> 2, c02 = (ch2 & 3) * 64;
                size_t tn = (size_t)(br * 9 + kh2 * 3 + kw2) * 16384;
                build_A_async(sb, (s2 & 1) ? OFF_A1 : OFF_A0, tid,
                              g_wAh + tn, g_wAl + tn, 128, c02 >> 1);
                CPA_COMMIT();
            }
            mma_chunk(sb, (step & 1) ? OFF_A1 : OFF_A0, offB, kw, wm, wn, lid, acc);
        }
    }

    const float* ob = (br == 0) ? ob0 : (br == 1) ? ob1 : (br == 2) ? ob2 : ob3;
    float* yb = g_y[br];
#pragma unroll
    for (int mt = 0; mt < 2; mt++) {
        int r0 = wm * 32 + mt * 16 + (lid >> 2);
#pragma unroll
        for (int half = 0; half < 2; half++) {
            int co = r0 + half * 8;
            float sh = ob[co];
            float* row = yb + ((size_t)(b * CMID + co) * HH + h) * WW;
#pragma unroll
            for (int nf = 0; nf < 4; nf++) {
                int px = wn * 32 + nf * 8 + 2 * (lid & 3);
                float2 v;
                v.x = fmaxf(acc[mt][nf][half * 2 + 0] + sh, 0.f);
                v.y = fmaxf(acc[mt][nf][half * 2 + 1] + sh, 0.f);
                *(float2*)(row + px) = v;
            }
        }
    }
}

// ---------------- scans along W (warp-per-row, float4 + shfl scan) ----------------
__global__ void k_scan_w()
{
    int bc   = blockIdx.x;
    int wq   = threadIdx.x >> 5;
    int lane = threadIdx.x & 31;
    const size_t plane = (size_t)bc * HH * WW;
    for (int hr = wq; hr < HH; hr += 16) {
        const float4* yl4 = (const float4*)(g_y[0] + plane + (size_t)hr * WW);
        const float4* yr4 = (const float4*)(g_y[1] + plane + (size_t)hr * WW);
        float4 a = yl4[lane];
        float4 r = yr4[lane];
        // forward cummax on r
        float p0 = r.x, p1 = fmaxf(p0, r.y), p2 = fmaxf(p1, r.z), p3 = fmaxf(p2, r.w);
        float m = p3;
#pragma unroll
        for (int o = 1; o < 32; o <<= 1) {
            float v = __shfl_up_sync(0xffffffffu, m, o);
            if (lane >= o) m = fmaxf(m, v);
        }
        float ex = __shfl_up_sync(0xffffffffu, m, 1);
        if (lane == 0) ex = -INFINITY;
        // reverse cummax on a
        float q3 = a.w, q2 = fmaxf(q3, a.z), q1 = fmaxf(q2, a.y), q0 = fmaxf(q1, a.x);
        float mm = q0;
#pragma unroll
        for (int o = 1; o < 32; o <<= 1) {
            float v = __shfl_down_sync(0xffffffffu, mm, o);
            if (lane + o < 32) mm = fmaxf(mm, v);
        }
        float exr = __shfl_down_sync(0xffffffffu, mm, 1);
        if (lane == 31) exr = -INFINITY;
        float4 o4;
        o4.x = fmaxf(ex, p0) + fmaxf(exr, q0);
        o4.y = fmaxf(ex, p1) + fmaxf(exr, q1);
        o4.z = fmaxf(ex, p2) + fmaxf(exr, q2);
        o4.w = fmaxf(ex, p3) + fmaxf(exr, q3);
        ((float4*)(g_S + plane + (size_t)hr * WW))[lane] = o4;
    }
}

// ---------------- scans along H (coalesced columns) ----------------
__global__ void k_scan_h()
{
    int bc = blockIdx.x;
    int w  = threadIdx.x;
    const float* yt = g_y[2] + (size_t)bc * (HH * WW) + w;
    const float* yv = g_y[3] + (size_t)bc * (HH * WW) + w;
    float* Sp = g_S + (size_t)bc * (HH * WW) + w;
    float m = -INFINITY;
    for (int hq = HH - 1; hq >= 0; --hq) { m = fmaxf(m, yt[hq * WW]); Sp[hq * WW] += m; }
    m = -INFINITY;
    for (int hq = 0; hq < HH; ++hq)      { m = fmaxf(m, yv[hq * WW]); Sp[hq * WW] += m; }
}

// ---------------- conv2 3x3 over S + 1x1 skip over x + relu -> out ----------------
// grid = (H=128, B=8, ct=2), 512 threads
// phase1: 6 chunks (kh x 2 c0) x 3 kw = 18 steps; phase2: 4 chunks x 1 step = 4 steps
__device__ __forceinline__ void prefetch_A_out(u32 sb, int tid, int ct, int s)
{
    if (s < 18) {
        int ch = s / 3, kw = s - ch * 3;
        int kh = ch >> 1, c0 = (ch & 1) * 64;
        size_t tn = ((size_t)(kh * 3 + kw) * 256 + ct * 128) * 64;
        build_A_async(sb, (s & 1) ? OFF_A1 : OFF_A0, tid, g_w2h + tn, g_w2l + tn, 64, c0 >> 1);
    } else {
        int c = s - 18;
        size_t tn = (size_t)(ct * 128) * 128;
        build_A_async(sb, (s & 1) ? OFF_A1 : OFF_A0, tid, g_w1h + tn, g_w1l + tn, 128, c * 32);
    }
    CPA_COMMIT();
}

__global__ __launch_bounds__(512, 1)
void k_conv_out(const float* __restrict__ x,
                const float* __restrict__ o2v, const float* __restrict__ o1v,
                float* __restrict__ out)
{
    extern __shared__ char smem_raw[];
    u32 sb = smem_u32(smem_raw);
    const int h  = blockIdx.x;
    const int b  = blockIdx.y;
    const int ct = blockIdx.z;
    const int tid = threadIdx.x;
    const int wid = tid >> 5, lid = tid & 31;
    const int wm = wid >> 2, wn = wid & 3;

    float acc[2][4][4];
#pragma unroll
    for (int i = 0; i < 2; i++)
#pragma unroll
        for (int j = 0; j < 4; j++)
#pragma unroll
            for (int k = 0; k < 4; k++) acc[i][j][k] = 0.f;

    BReg breg;
    ldg_B(breg, tid, g_S, CMID, b, 0, h - 1);        // phase1 chunk 0
    prefetch_A_out(sb, tid, ct, 0);

    // phase 1: 3x3 conv over g_S
    for (int ch = 0; ch < 6; ch++) {
        u32 offB = (ch & 1) ? OFF_B1 : OFF_B0;
        st_B(breg, sb, offB, tid);
        __syncthreads();
        if (ch + 1 < 6) {
            int kh2 = (ch + 1) >> 1, c02 = ((ch + 1) & 1) * 64;
            ldg_B(breg, tid, g_S, CMID, b, c02, h + kh2 - 1);
        } else {
            ldg_B(breg, tid, x, CINC, b, 0, h);      // bridge to phase 2
        }
#pragma unroll
        for (int kw = 0; kw < 3; kw++) {
            int step = ch * 3 + kw;
            CPA_WAIT0();
            __syncthreads();
            if (step + 1 < 22) prefetch_A_out(sb, tid, ct, step + 1);
            mma_chunk(sb, (step & 1) ? OFF_A1 : OFF_A0, offB, kw, wm, wn, lid, acc);
        }
    }
    // phase 2: 1x1 skip over x (brow offset = 1 reads unshifted pixels)
    for (int c = 0; c < 4; c++) {
        int ch = 6 + c;
        u32 offB = (ch & 1) ? OFF_B1 : OFF_B0;
        st_B(breg, sb, offB, tid);
        __syncthreads();
        if (c + 1 < 4) ldg_B(breg, tid, x, CINC, b, (c + 1) * 64, h);
        int step = 18 + c;
        CPA_WAIT0();
        __syncthreads();
        if (step + 1 < 22) prefetch_A_out(sb, tid, ct, step + 1);
        mma_chunk(sb, (step & 1) ? OFF_A1 : OFF_A0, offB, 1, wm, wn, lid, acc);
    }

#pragma unroll
    for (int mt = 0; mt < 2; mt++) {
        int r0 = wm * 32 + mt * 16 + (lid >> 2);
#pragma unroll
        for (int half = 0; half < 2; half++) {
            int co = ct * 128 + r0 + half * 8;
            float sh = o2v[co] + o1v[co];
            float* row = out + ((size_t)(b * COUTC + co) * HH + h) * WW;
#pragma unroll
            for (int nf = 0; nf < 4; nf++) {
                int px = wn * 32 + nf * 8 + 2 * (lid & 3);
                float2 v;
                v.x = fmaxf(acc[mt][nf][half * 2 + 0] + sh, 0.f);
                v.y = fmaxf(acc[mt][nf][half * 2 + 1] + sh, 0.f);
                *(float2*)(row + px) = v;
            }
        }
    }
}

// ---------------- launch ----------------
extern "C" void kernel_launch(void* const* d_in, const int* in_sizes, int n_in,
                              void* d_out, int out_size)
{
    const float* x   = (const float*)d_in[0];
    const float* w_l = (const float*)d_in[1];
    const float* s_l = (const float*)d_in[2];
    const float* o_l = (const float*)d_in[3];
    const float* w_r = (const float*)d_in[4];
    const float* s_r = (const float*)d_in[5];
    const float* o_r = (const float*)d_in[6];
    const float* w_t = (const float*)d_in[7];
    const float* s_t = (const float*)d_in[8];
    const float* o_t = (const float*)d_in[9];
    const float* w_b = (const float*)d_in[10];
    const float* s_b = (const float*)d_in[11];
    const float* o_b = (const float*)d_in[12];
    const float* w2  = (const float*)d_in[13];
    const float* s2  = (const float*)d_in[14];
    const float* o2  = (const float*)d_in[15];
    const float* w1  = (const float*)d_in[16];
    const float* s1  = (const float*)d_in[17];
    const float* o1  = (const float*)d_in[18];
    float* out = (float*)d_out;

    cudaFuncSetAttribute(k_conv_branch, cudaFuncAttributeMaxDynamicSharedMemorySize, SMEM_BYTES);
    cudaFuncSetAttribute(k_conv_out,    cudaFuncAttributeMaxDynamicSharedMemorySize, SMEM_BYTES);

    k_repack_br<<<576, 256>>>(w_l, s_l, 0);
    k_repack_br<<<576, 256>>>(w_r, s_r, 1);
    k_repack_br<<<576, 256>>>(w_t, s_t, 2);
    k_repack_br<<<576, 256>>>(w_b, s_b, 3);
    k_repack_w2<<<576, 256>>>(w2, s2);
    k_repack_w1<<<128, 256>>>(w1, s1);

    dim3 g1(HH, BN, 4);
    k_conv_branch<<<g1, 512, SMEM_BYTES>>>(x, o_l, o_r, o_t, o_b);
    k_scan_w<<<BN * CMID, 512>>>();
    k_scan_h<<<BN * CMID, 128>>>();
    dim3 g3(HH, BN, 2);
    k_conv_out<<<g3, 512, SMEM_BYTES>>>(x, o2, o1, out);
}